// round 5
// baseline (speedup 1.0000x reference)
#include <cuda_runtime.h>
#include <cuda_bf16.h>
#include <stdint.h>

#define NODES_CAP 100000     // scratch capacity (matches dataset N)
#define DIM       32

// Scratch for XW = X @ W (12.8 MB). Static __device__ global — no allocation.
__device__ float g_XW[NODES_CAP * DIM];

// ---------------------------------------------------------------------------
// Kernel 1: XW[r][j] = sum_k X[r][k] * W[k][j]
// One warp per row; lane j owns output feature j. W staged in shared memory.
// X is read once -> streaming loads. g_XW stores left cacheable (hot set).
// ---------------------------------------------------------------------------
__global__ void __launch_bounds__(256)
xw_kernel(const float* __restrict__ X, const float* __restrict__ W, int n)
{
    __shared__ float Ws[DIM * DIM];
    int tid = threadIdx.x;
    #pragma unroll
    for (int i = tid; i < DIM * DIM; i += 256)
        Ws[i] = W[i];
    __syncthreads();

    int warp = (blockIdx.x * 256 + tid) >> 5;
    int lane = tid & 31;
    if (warp >= n) return;

    float x = __ldcs(&X[warp * DIM + lane]);   // lane k holds X[row][k]
    float acc = 0.0f;
    #pragma unroll
    for (int k = 0; k < DIM; k++) {
        float xk = __shfl_sync(0xffffffffu, x, k);
        acc = fmaf(xk, Ws[k * DIM + lane], acc);
    }
    g_XW[warp * DIM + lane] = acc;
}

// ---------------------------------------------------------------------------
// Kernel 2: out[r][lane] = sum over e in [rp[r], rp[r+1]) of XW[ci[e]][lane]
// One warp per row. Indices loaded 32-at-a-time coalesced (streaming -- read
// once), broadcast via shuffle; gathers unrolled x8 (then x4, then scalar)
// so many independent 128B L2 loads are in flight (XW is L2-resident).
// Dual accumulators shorten the cross-batch FADD chain. Output stored
// streaming to avoid polluting L2.
// ---------------------------------------------------------------------------
__global__ void __launch_bounds__(256)
gather_kernel(const int* __restrict__ rp, const int* __restrict__ ci,
              float* __restrict__ out, int n)
{
    int warp = (blockIdx.x * 256 + threadIdx.x) >> 5;
    int lane = threadIdx.x & 31;
    if (warp >= n) return;

    int beg = __ldg(&rp[warp]);
    int end = __ldg(&rp[warp + 1]);

    const float* __restrict__ xw = g_XW + lane;   // lane-fixed base
    float acc0 = 0.0f, acc1 = 0.0f;

    for (int base = beg; base < end; base += 32) {
        int m = end - base;
        if (m > 32) m = 32;
        // One coalesced streaming load covers up to 32 edge indices.
        int c = (lane < m) ? __ldcs(&ci[base + lane]) : 0;

        int k = 0;
        // 8-wide unrolled broadcast+gather: 8 independent LDGs in flight.
        for (; k + 8 <= m; k += 8) {
            int i0 = __shfl_sync(0xffffffffu, c, k + 0);
            int i1 = __shfl_sync(0xffffffffu, c, k + 1);
            int i2 = __shfl_sync(0xffffffffu, c, k + 2);
            int i3 = __shfl_sync(0xffffffffu, c, k + 3);
            int i4 = __shfl_sync(0xffffffffu, c, k + 4);
            int i5 = __shfl_sync(0xffffffffu, c, k + 5);
            int i6 = __shfl_sync(0xffffffffu, c, k + 6);
            int i7 = __shfl_sync(0xffffffffu, c, k + 7);
            float v0 = xw[i0 * DIM];
            float v1 = xw[i1 * DIM];
            float v2 = xw[i2 * DIM];
            float v3 = xw[i3 * DIM];
            float v4 = xw[i4 * DIM];
            float v5 = xw[i5 * DIM];
            float v6 = xw[i6 * DIM];
            float v7 = xw[i7 * DIM];
            acc0 += (v0 + v1) + (v2 + v3);
            acc1 += (v4 + v5) + (v6 + v7);
        }
        // 4-wide step keeps MLP up on the common tail (deg%8 in 1..7).
        if (k + 4 <= m) {
            int i0 = __shfl_sync(0xffffffffu, c, k + 0);
            int i1 = __shfl_sync(0xffffffffu, c, k + 1);
            int i2 = __shfl_sync(0xffffffffu, c, k + 2);
            int i3 = __shfl_sync(0xffffffffu, c, k + 3);
            float v0 = xw[i0 * DIM];
            float v1 = xw[i1 * DIM];
            float v2 = xw[i2 * DIM];
            float v3 = xw[i3 * DIM];
            acc0 += (v0 + v1);
            acc1 += (v2 + v3);
            k += 4;
        }
        for (; k < m; k++) {
            int i0 = __shfl_sync(0xffffffffu, c, k);
            acc0 += xw[i0 * DIM];
        }
    }

    __stcs(&out[warp * DIM + lane], acc0 + acc1);  // 0 for empty rows
}

// ---------------------------------------------------------------------------
// Launch
// Inputs (metadata order): 0=X [N*32 f32], 1=weights [32*32 f32],
// 2=row_pointers [N+1 i32], 3=column_index [E i32], 4..=dummies.
// Output: [N*32] f32.
// ---------------------------------------------------------------------------
extern "C" void kernel_launch(void* const* d_in, const int* in_sizes, int n_in,
                              void* d_out, int out_size)
{
    const float* X  = (const float*)d_in[0];
    const float* W  = (const float*)d_in[1];
    const int*   rp = (const int*)d_in[2];
    const int*   ci = (const int*)d_in[3];
    float*       out = (float*)d_out;

    int n = in_sizes[2] - 1;          // rows from row_pointers length
    if (n > NODES_CAP) n = NODES_CAP; // scratch capacity guard

    const int warps_per_block = 256 / 32;
    const int blocks = (n + warps_per_block - 1) / warps_per_block;

    xw_kernel<<<blocks, 256>>>(X, W, n);
    gather_kernel<<<blocks, 256>>>(rp, ci, out, n);
}

// round 9
// speedup vs baseline: 1.4285x; 1.4285x over previous
#include <cuda_runtime.h>
#include <cuda_bf16.h>
#include <stdint.h>

#define NODES_CAP 100000     // scratch capacity (matches dataset N)
#define DIM       32

// Scratch for XW = X @ W (12.8 MB). Static __device__ global — no allocation.
__device__ float g_XW[NODES_CAP * DIM];

// ---------------------------------------------------------------------------
// Kernel 1: XW[r][j] = sum_k X[r][k] * W[k][j]
// Block = 256 threads = 8 warps, 16 rows per warp (128 rows/block).
// No shuffles: each lane holds W[:,lane] in 32 registers; x values come from
// a shared-memory X tile via uniform LDS.128 (4 k-values per load).
// ---------------------------------------------------------------------------
#define XW_ROWS_PER_BLOCK 128
#define XW_ROWS_PER_WARP  16

__global__ void __launch_bounds__(256)
xw_kernel(const float* __restrict__ X, const float* __restrict__ W, int n)
{
    __shared__ float Ws[DIM * DIM];                    // 4 KB
    __shared__ float Xs[XW_ROWS_PER_BLOCK * DIM];      // 16 KB

    int tid  = threadIdx.x;
    int warp = tid >> 5;
    int lane = tid & 31;
    int row0 = blockIdx.x * XW_ROWS_PER_BLOCK;
    int rows = n - row0;
    if (rows > XW_ROWS_PER_BLOCK) rows = XW_ROWS_PER_BLOCK;

    // Stage W (coalesced) and the X tile (coalesced float4).
    #pragma unroll
    for (int i = tid; i < DIM * DIM; i += 256)
        Ws[i] = W[i];
    {
        const float4* __restrict__ X4 = (const float4*)(X + (size_t)row0 * DIM);
        float4* Xs4 = (float4*)Xs;
        int n4 = rows * (DIM / 4);
        for (int i = tid; i < n4; i += 256)
            Xs4[i] = __ldcs(&X4[i]);
    }
    __syncthreads();

    // Each lane caches its W column in registers.
    float wc[DIM];
    #pragma unroll
    for (int k = 0; k < DIM; k++)
        wc[k] = Ws[k * DIM + lane];

    #pragma unroll 4
    for (int r = 0; r < XW_ROWS_PER_WARP; r++) {
        int lrow = warp * XW_ROWS_PER_WARP + r;
        if (lrow >= rows) break;
        const float4* xs = (const float4*)(Xs + lrow * DIM);  // uniform addr
        float acc = 0.0f;
        #pragma unroll
        for (int kk = 0; kk < DIM / 4; kk++) {
            float4 x4 = xs[kk];
            acc = fmaf(x4.x, wc[4 * kk + 0], acc);
            acc = fmaf(x4.y, wc[4 * kk + 1], acc);
            acc = fmaf(x4.z, wc[4 * kk + 2], acc);
            acc = fmaf(x4.w, wc[4 * kk + 3], acc);
        }
        g_XW[(size_t)(row0 + lrow) * DIM + lane] = acc;
    }
}

// ---------------------------------------------------------------------------
// Kernel 2: out[r][:] = sum over e in [rp[r], rp[r+1]) of XW[ci[e]][:]
// One warp per row. Lane mapping: eo = lane>>3 selects 1 of 4 edges,
// fo = lane&7 selects a float4 chunk of the 32-float row. One warp LDG.128
// gathers 4 edges x 128B. Main loop handles 8 edges (2 groups) per
// iteration, unrolled x2 by the compiler for 4 gathers in flight; single
// predicated tail pair. No per-edge shuffles — only an 8-shuffle cross-eo
// reduction at the end.
// ---------------------------------------------------------------------------
__global__ void __launch_bounds__(256)
gather_kernel(const int* __restrict__ rp, const int* __restrict__ ci,
              float* __restrict__ out, int n)
{
    int warp = (blockIdx.x * 256 + threadIdx.x) >> 5;
    int lane = threadIdx.x & 31;
    if (warp >= n) return;

    int beg = __ldg(&rp[warp]);
    int end = __ldg(&rp[warp + 1]);

    int eo = lane >> 3;        // which of 4 edges in a group
    int fo = lane & 7;         // which float4 chunk of the row

    const float4* __restrict__ xw4 = (const float4*)g_XW;

    float4 a0 = make_float4(0.f, 0.f, 0.f, 0.f);
    float4 a1 = make_float4(0.f, 0.f, 0.f, 0.f);

    int deg      = end - beg;
    int full_end = beg + (deg & ~7);
    int base     = beg;

    // Main loop: 8 edges per iteration, fully unconditional.
    #pragma unroll 2
    for (; base < full_end; base += 8) {
        int i0 = __ldcs(&ci[base + eo]);
        int i1 = __ldcs(&ci[base + 4 + eo]);
        float4 t0 = xw4[i0 * 8 + fo];
        float4 t1 = xw4[i1 * 8 + fo];
        a0.x += t0.x; a0.y += t0.y; a0.z += t0.z; a0.w += t0.w;
        a1.x += t1.x; a1.y += t1.y; a1.z += t1.z; a1.w += t1.w;
    }

    // Tail: up to 7 edges, two predicated groups.
    if (base < end) {
        int e0 = base + eo;
        int e1 = base + 4 + eo;
        if (e0 < end) {
            int i0 = __ldcs(&ci[e0]);
            float4 t0 = xw4[i0 * 8 + fo];
            a0.x += t0.x; a0.y += t0.y; a0.z += t0.z; a0.w += t0.w;
        }
        if (e1 < end) {
            int i1 = __ldcs(&ci[e1]);
            float4 t1 = xw4[i1 * 8 + fo];
            a1.x += t1.x; a1.y += t1.y; a1.z += t1.z; a1.w += t1.w;
        }
    }

    float4 acc;
    acc.x = a0.x + a1.x;
    acc.y = a0.y + a1.y;
    acc.z = a0.z + a1.z;
    acc.w = a0.w + a1.w;

    // Reduce across the 4 eo groups (lanes differing in bits 3 and 4).
    #pragma unroll
    for (int m = 8; m <= 16; m <<= 1) {
        acc.x += __shfl_xor_sync(0xffffffffu, acc.x, m);
        acc.y += __shfl_xor_sync(0xffffffffu, acc.y, m);
        acc.z += __shfl_xor_sync(0xffffffffu, acc.z, m);
        acc.w += __shfl_xor_sync(0xffffffffu, acc.w, m);
    }

    // Lanes 0-7 hold the full row sum for their chunk: one 128B store.
    if (lane < 8) {
        float4* out4 = (float4*)(out + (size_t)warp * DIM);
        __stcs(&out4[fo], acc);    // 0 for empty rows (d_out poisoned)
    }
}

// ---------------------------------------------------------------------------
// Launch
// Inputs (metadata order): 0=X [N*32 f32], 1=weights [32*32 f32],
// 2=row_pointers [N+1 i32], 3=column_index [E i32], 4..=dummies.
// Output: [N*32] f32.
// ---------------------------------------------------------------------------
extern "C" void kernel_launch(void* const* d_in, const int* in_sizes, int n_in,
                              void* d_out, int out_size)
{
    const float* X  = (const float*)d_in[0];
    const float* W  = (const float*)d_in[1];
    const int*   rp = (const int*)d_in[2];
    const int*   ci = (const int*)d_in[3];
    float*       out = (float*)d_out;

    int n = in_sizes[2] - 1;          // rows from row_pointers length
    if (n > NODES_CAP) n = NODES_CAP; // scratch capacity guard

    int xw_blocks = (n + XW_ROWS_PER_BLOCK - 1) / XW_ROWS_PER_BLOCK;
    xw_kernel<<<xw_blocks, 256>>>(X, W, n);

    const int warps_per_block = 256 / 32;
    int g_blocks = (n + warps_per_block - 1) / warps_per_block;
    gather_kernel<<<g_blocks, 256>>>(rp, ci, out, n);
}